// round 9
// baseline (speedup 1.0000x reference)
#include <cuda_runtime.h>
#include <cstdint>

// Problem constants
#define B 128
#define T 512
#define I 50
#define H 256
#define K_SMEM 96           // k-range of W kept in shared memory
#define K_REG  160          // k-range of W kept in registers
#define PITCH 100           // smem pitch in floats (conflict-free LDS.128)

// Scratch: xp[dir][t][b][h]  (fp32), 134 MB
__device__ float g_xp[2u * T * B * H];

// ---------------------------------------------------------------------------
// packed fp32x2 helpers (Blackwell)
// ---------------------------------------------------------------------------
__device__ __forceinline__ unsigned long long ffma2(unsigned long long a,
                                                    unsigned long long b,
                                                    unsigned long long c) {
    unsigned long long d;
    asm("fma.rn.f32x2 %0, %1, %2, %3;" : "=l"(d) : "l"(a), "l"(b), "l"(c));
    return d;
}
__device__ __forceinline__ float2 u2f(unsigned long long v) {
    float2 f;
    asm("mov.b64 {%0, %1}, %2;" : "=f"(f.x), "=f"(f.y) : "l"(v));
    return f;
}
__device__ __forceinline__ unsigned long long f2u(float lo, float hi) {
    unsigned long long v;
    asm("mov.b64 %0, {%1, %2};" : "=l"(v) : "f"(lo), "f"(hi));
    return v;
}

// ---------------------------------------------------------------------------
// Kernel 1: direction-fused input projection, batch-split across 2 blocks.
// Block (t, bh) stages x[bh*64:(bh+1)*64, t, :] once; thread h holds BOTH
// w_ih_f[h] and w_ih_b[h] rows in registers and writes fwd xp[0][t] and
// bwd xp[1][T-1-t] for its 64 batch rows.
// ---------------------------------------------------------------------------
#define IPAD 52
#define BCHUNK 64
__global__ __launch_bounds__(256) void proj_kernel(
    const float* __restrict__ x,
    const float* __restrict__ w_ih_f, const float* __restrict__ b_ih_f, const float* __restrict__ b_hh_f,
    const float* __restrict__ w_ih_b, const float* __restrict__ b_ih_b, const float* __restrict__ b_hh_b)
{
    __shared__ float xs[BCHUNK * IPAD];   // 13.3 KB, padded rows

    const int t  = blockIdx.x;
    const int bh = blockIdx.y;
    const int h  = threadIdx.x;
    const int bbase = bh * BCHUNK;

    // zero padding lanes, then stage x[bbase:bbase+64, t, :]
    for (int idx = h; idx < BCHUNK * IPAD; idx += blockDim.x) xs[idx] = 0.f;
    __syncthreads();
    for (int idx = h; idx < BCHUNK * I; idx += blockDim.x) {
        int b = idx / I;
        int i = idx - b * I;
        xs[b * IPAD + i] = x[((size_t)(bbase + b) * T + t) * I + i];
    }

    // both directions' weight rows in registers (packed pairs, zero-padded)
    unsigned long long wf[26], wb[26];
    {
        const float* pf = w_ih_f + (size_t)h * I;
        const float* pb = w_ih_b + (size_t)h * I;
        #pragma unroll
        for (int i = 0; i < 25; i++) {
            wf[i] = f2u(pf[2 * i], pf[2 * i + 1]);
            wb[i] = f2u(pb[2 * i], pb[2 * i + 1]);
        }
        wf[25] = 0ull;
        wb[25] = 0ull;
    }
    const float biasf = b_ih_f[h] + b_hh_f[h];
    const float biasb = b_ih_b[h] + b_hh_b[h];

    __syncthreads();

    float* xpf = g_xp + (((size_t)0 * T + t) * B + bbase) * H + h;            // fwd step t
    float* xpb = g_xp + (((size_t)1 * T + (T - 1 - t)) * B + bbase) * H + h;  // bwd step T-1-t
    #pragma unroll 2
    for (int b = 0; b < BCHUNK; b++) {
        const ulonglong2* xb = reinterpret_cast<const ulonglong2*>(&xs[b * IPAD]);
        unsigned long long f0 = 0ull, f1 = 0ull, g0 = 0ull, g1 = 0ull;
        #pragma unroll
        for (int i = 0; i < 13; i++) {
            ulonglong2 xv = xb[i];
            f0 = ffma2(xv.x, wf[2 * i],     f0);
            f1 = ffma2(xv.y, wf[2 * i + 1], f1);
            g0 = ffma2(xv.x, wb[2 * i],     g0);
            g1 = ffma2(xv.y, wb[2 * i + 1], g1);
        }
        float2 a0 = u2f(f0), a1 = u2f(f1);
        float2 c0 = u2f(g0), c1 = u2f(g1);
        xpf[(size_t)b * H] = biasf + ((a0.x + a0.y) + (a1.x + a1.y));
        xpb[(size_t)b * H] = biasb + ((c0.x + c0.y) + (c1.x + c1.y));
    }
}

// ---------------------------------------------------------------------------
// Kernel 2: recurrence — R2 memory ops / counts / registers, with the inner
// loop INTERLEAVED: 8 groups of {3 smem-W iters + 5 reg-W iters} so FFMA2
// work overlaps the crossbar-heavy W-smem reads instead of running in two
// separate phases.
// ---------------------------------------------------------------------------
__global__ __launch_bounds__(256, 1) void rnn_kernel(
    const float* __restrict__ w_hh_f,
    const float* __restrict__ w_hh_b,
    float* __restrict__ out)
{
    extern __shared__ float sm[];
    float* Wsh = sm;                       // [256][PITCH]  (102,400 B)
    float* hs  = sm + 256 * PITCH;         // [2 buf][2 rows][256]  (4,096 B)

    const int dir = blockIdx.x >> 6;
    const int j   = blockIdx.x & 63;
    const int b0  = 2 * j;
    const int t   = threadIdx.x;

    const float* __restrict__ W = dir ? w_hh_b : w_hh_f;

    // W[:, 0:K_SMEM] -> smem
    for (int idx = t; idx < 256 * K_SMEM; idx += 256) {
        int n = idx / K_SMEM;
        int k = idx - n * K_SMEM;
        Wsh[n * PITCH + k] = W[n * H + k];
    }
    // W[t, K_SMEM:256] -> regs, as packed (k,k+1) pairs
    ulonglong2 wreg[K_REG / 4];            // 40 x 16B = 160 floats
    {
        const ulonglong2* wrow = reinterpret_cast<const ulonglong2*>(W + (size_t)t * H + K_SMEM);
        #pragma unroll
        for (int r = 0; r < K_REG / 4; r++) wreg[r] = wrow[r];
    }
    hs[0 * 512 + 0 * 256 + t] = 0.f;
    hs[0 * 512 + 1 * 256 + t] = 0.f;
    __syncthreads();

    const float* xp0 = g_xp + ((size_t)dir * T * B + b0) * H + t;
    const float* xp1 = xp0 + H;
    const size_t step_stride = (size_t)B * H;

    float xa = __ldg(xp0);
    float xb = __ldg(xp1);

    float* out_t = out + (size_t)dir * H + t;

    int buf = 0;
    for (int s = 0; s < T; s++) {
        float nxa = 0.f, nxb = 0.f;
        if (s < T - 1) {
            nxa = __ldg(xp0 + (size_t)(s + 1) * step_stride);
            nxb = __ldg(xp1 + (size_t)(s + 1) * step_stride);
        }

        const ulonglong2* h0v = reinterpret_cast<const ulonglong2*>(hs + buf * 512);
        const ulonglong2* h1v = reinterpret_cast<const ulonglong2*>(hs + buf * 512 + 256);
        const ulonglong2* wv  = reinterpret_cast<const ulonglong2*>(Wsh + t * PITCH);

        // 4 independent packed accumulator chains (2 per batch row)
        unsigned long long aA0 = 0ull, aB0 = 0ull, aA1 = 0ull, aB1 = 0ull;

        // interleaved: 8 groups of (3 smem-W iters + 5 reg-W iters)
        #pragma unroll
        for (int g = 0; g < 8; g++) {
            #pragma unroll
            for (int ii = 0; ii < 3; ii++) {
                const int i = 3 * g + ii;                 // smem iter, k = 4i in [0,96)
                ulonglong2 w  = wv[i];
                ulonglong2 ha = h0v[i];
                ulonglong2 hb = h1v[i];
                aA0 = ffma2(w.x, ha.x, aA0);
                aB0 = ffma2(w.y, ha.y, aB0);
                aA1 = ffma2(w.x, hb.x, aA1);
                aB1 = ffma2(w.y, hb.y, aB1);
            }
            #pragma unroll
            for (int rr = 0; rr < 5; rr++) {
                const int r = 5 * g + rr;                 // reg iter, k = 96+4r
                ulonglong2 w  = wreg[r];
                ulonglong2 ha = h0v[K_SMEM / 4 + r];
                ulonglong2 hb = h1v[K_SMEM / 4 + r];
                aA0 = ffma2(w.x, ha.x, aA0);
                aB0 = ffma2(w.y, ha.y, aB0);
                aA1 = ffma2(w.x, hb.x, aA1);
                aB1 = ffma2(w.y, hb.y, aB1);
            }
        }

        float2 fA0 = u2f(aA0), fB0 = u2f(aB0);
        float2 fA1 = u2f(aA1), fB1 = u2f(aB1);
        float h0 = fmaxf(xa + ((fA0.x + fA0.y) + (fB0.x + fB0.y)), 0.f);
        float h1 = fmaxf(xb + ((fA1.x + fA1.y) + (fB1.x + fB1.y)), 0.f);

        const int time = dir ? (T - 1 - s) : s;
        out_t[((size_t)b0 * T + time) * (2 * H)] = h0;
        out_t[((size_t)(b0 + 1) * T + time) * (2 * H)] = h1;

        const int nb = buf ^ 1;
        hs[nb * 512 + t]       = h0;
        hs[nb * 512 + 256 + t] = h1;
        __syncthreads();

        buf = nb;
        xa = nxa;
        xb = nxb;
    }
}

// ---------------------------------------------------------------------------
extern "C" void kernel_launch(void* const* d_in, const int* in_sizes, int n_in,
                              void* d_out, int out_size)
{
    const float* x      = (const float*)d_in[0];
    const float* w_ih_f = (const float*)d_in[1];
    const float* w_hh_f = (const float*)d_in[2];
    const float* b_ih_f = (const float*)d_in[3];
    const float* b_hh_f = (const float*)d_in[4];
    const float* w_ih_b = (const float*)d_in[5];
    const float* w_hh_b = (const float*)d_in[6];
    const float* b_ih_b = (const float*)d_in[7];
    const float* b_hh_b = (const float*)d_in[8];
    float* out = (float*)d_out;

    static bool attr_set = false;
    const int smem_bytes = 256 * PITCH * 4 + 2 * 2 * 256 * 4;  // 106,496 B
    if (!attr_set) {
        cudaFuncSetAttribute(rnn_kernel, cudaFuncAttributeMaxDynamicSharedMemorySize, smem_bytes);
        attr_set = true;
    }

    // 1) direction-fused input projection, batch split in 2 (T x 2 blocks)
    proj_kernel<<<dim3(T, 2), 256>>>(x, w_ih_f, b_ih_f, b_hh_f, w_ih_b, b_ih_b, b_hh_b);

    // 2) recurrence: 128 CTAs (64 per direction, 2 batch rows each)
    rnn_kernel<<<128, 256, smem_bytes>>>(w_hh_f, w_hh_b, out);
}

// round 10
// speedup vs baseline: 1.1901x; 1.1901x over previous
#include <cuda_runtime.h>
#include <cstdint>

// Problem constants
#define B 128
#define T 512
#define I 50
#define H 256
#define K_SMEM 96           // k-range of W kept in shared memory
#define K_REG  160          // k-range of W kept in registers
#define PITCH 100           // smem pitch in floats (conflict-free LDS.128)

// Scratch: xp[dir][t][b][h]  (fp32), 2*512*128*256 floats = 134 MB
__device__ float g_xp[2u * T * B * H];

// ---------------------------------------------------------------------------
// packed fp32x2 helpers (Blackwell)
// ---------------------------------------------------------------------------
__device__ __forceinline__ unsigned long long ffma2(unsigned long long a,
                                                    unsigned long long b,
                                                    unsigned long long c) {
    unsigned long long d;
    asm("fma.rn.f32x2 %0, %1, %2, %3;" : "=l"(d) : "l"(a), "l"(b), "l"(c));
    return d;
}
__device__ __forceinline__ float2 u2f(unsigned long long v) {
    float2 f;
    asm("mov.b64 {%0, %1}, %2;" : "=f"(f.x), "=f"(f.y) : "l"(v));
    return f;
}
__device__ __forceinline__ unsigned long long f2u(float lo, float hi) {
    unsigned long long v;
    asm("mov.b64 %0, {%1, %2};" : "=l"(v) : "f"(lo), "f"(hi));
    return v;
}

// ---------------------------------------------------------------------------
// Kernel 1: input projection, 2 neurons per thread (x-broadcast reuse x2).
// Grid T blocks, 256 threads. Thread: h2 = tid&127 -> neurons {2h2, 2h2+1},
// dir = tid>>7. Block stages x[:, t, :] once; each x broadcast LDS now fuels
// 8 MACs/lane (2 neurons x packed pair) instead of 4, halving the dominant
// LDS-wavefront term (~50us -> ~25us, hidden under the ~47us FMA stream).
// fwd writes timestep t; bwd writes timestep T-1-t (both consume x[:, t, :]).
// ---------------------------------------------------------------------------
#define IPAD 52
__global__ __launch_bounds__(256) void proj_kernel(
    const float* __restrict__ x,
    const float* __restrict__ w_ih_f, const float* __restrict__ b_ih_f, const float* __restrict__ b_hh_f,
    const float* __restrict__ w_ih_b, const float* __restrict__ b_ih_b, const float* __restrict__ b_hh_b)
{
    __shared__ float xs[B * IPAD];   // 26.6 KB, padded rows

    const int t   = blockIdx.x;
    const int tid = threadIdx.x;
    const int h2  = tid & 127;       // neuron pair index
    const int dir = tid >> 7;        // 0 = fwd, 1 = bwd

    // zero padding lanes, then stage x[:, t, :]
    for (int idx = tid; idx < B * IPAD; idx += blockDim.x) xs[idx] = 0.f;
    __syncthreads();
    for (int idx = tid; idx < B * I; idx += blockDim.x) {
        int b = idx / I;
        int i = idx - b * I;
        xs[b * IPAD + i] = x[((size_t)b * T + t) * I + i];
    }

    // 2 weight rows of this thread's direction, packed pairs (zero-padded to 26)
    const float* w    = dir ? w_ih_b : w_ih_f;
    const float* bih  = dir ? b_ih_b : b_ih_f;
    const float* bhh  = dir ? b_hh_b : b_hh_f;
    unsigned long long w0[26], w1[26];
    {
        const float* p0 = w + (size_t)(2 * h2) * I;
        const float* p1 = w + (size_t)(2 * h2 + 1) * I;
        #pragma unroll
        for (int i = 0; i < 25; i++) {
            w0[i] = f2u(p0[2 * i], p0[2 * i + 1]);
            w1[i] = f2u(p1[2 * i], p1[2 * i + 1]);
        }
        w0[25] = 0ull;
        w1[25] = 0ull;
    }
    const float bias0 = bih[2 * h2]     + bhh[2 * h2];
    const float bias1 = bih[2 * h2 + 1] + bhh[2 * h2 + 1];

    __syncthreads();

    const int tw = dir ? (T - 1 - t) : t;
    float* xp_out = g_xp + (((size_t)dir * T + tw) * B) * H + 2 * h2;
    #pragma unroll 2
    for (int b = 0; b < B; b++) {
        const ulonglong2* xb = reinterpret_cast<const ulonglong2*>(&xs[b * IPAD]);
        unsigned long long a00 = 0ull, a01 = 0ull, a10 = 0ull, a11 = 0ull;
        #pragma unroll
        for (int i = 0; i < 13; i++) {
            ulonglong2 xv = xb[i];
            a00 = ffma2(xv.x, w0[2 * i],     a00);
            a01 = ffma2(xv.y, w0[2 * i + 1], a01);
            a10 = ffma2(xv.x, w1[2 * i],     a10);
            a11 = ffma2(xv.y, w1[2 * i + 1], a11);
        }
        float2 f00 = u2f(a00), f01 = u2f(a01);
        float2 f10 = u2f(a10), f11 = u2f(a11);
        float2 o;
        o.x = bias0 + ((f00.x + f00.y) + (f01.x + f01.y));
        o.y = bias1 + ((f10.x + f10.y) + (f11.x + f11.y));
        *reinterpret_cast<float2*>(xp_out + (size_t)b * H) = o;
    }
}

// ---------------------------------------------------------------------------
// Kernel 2: recurrence — BYTE-EXACT round-2 version (measured 781-825 us).
// DO NOT MODIFY: every reordering/micro-op change (R7 fadd2+uncond prefetch,
// R9 interleave) regressed it by 15-25%. ptxas's schedule of this exact
// source is the local optimum.
// ---------------------------------------------------------------------------
__global__ __launch_bounds__(256, 1) void rnn_kernel(
    const float* __restrict__ w_hh_f,
    const float* __restrict__ w_hh_b,
    float* __restrict__ out)
{
    extern __shared__ float sm[];
    float* Wsh = sm;                       // [256][PITCH]  (102,400 B)
    float* hs  = sm + 256 * PITCH;         // [2 buf][2 rows][256]  (4,096 B)

    const int dir = blockIdx.x >> 6;
    const int j   = blockIdx.x & 63;
    const int b0  = 2 * j;
    const int t   = threadIdx.x;

    const float* __restrict__ W = dir ? w_hh_b : w_hh_f;

    // W[:, 0:K_SMEM] -> smem
    for (int idx = t; idx < 256 * K_SMEM; idx += 256) {
        int n = idx / K_SMEM;
        int k = idx - n * K_SMEM;
        Wsh[n * PITCH + k] = W[n * H + k];
    }
    // W[t, K_SMEM:256] -> regs, as packed (k,k+1) pairs
    ulonglong2 wreg[K_REG / 4];            // 40 x 16B = 160 floats
    {
        const ulonglong2* wrow = reinterpret_cast<const ulonglong2*>(W + (size_t)t * H + K_SMEM);
        #pragma unroll
        for (int r = 0; r < K_REG / 4; r++) wreg[r] = wrow[r];
    }
    hs[0 * 512 + 0 * 256 + t] = 0.f;
    hs[0 * 512 + 1 * 256 + t] = 0.f;
    __syncthreads();

    const float* xp0 = g_xp + ((size_t)dir * T * B + b0) * H + t;
    const float* xp1 = xp0 + H;
    const size_t step_stride = (size_t)B * H;

    float xa = __ldg(xp0);
    float xb = __ldg(xp1);

    float* out_t = out + (size_t)dir * H + t;

    int buf = 0;
    for (int s = 0; s < T; s++) {
        float nxa = 0.f, nxb = 0.f;
        if (s < T - 1) {
            nxa = __ldg(xp0 + (size_t)(s + 1) * step_stride);
            nxb = __ldg(xp1 + (size_t)(s + 1) * step_stride);
        }

        const ulonglong2* h0v = reinterpret_cast<const ulonglong2*>(hs + buf * 512);
        const ulonglong2* h1v = reinterpret_cast<const ulonglong2*>(hs + buf * 512 + 256);
        const ulonglong2* wv  = reinterpret_cast<const ulonglong2*>(Wsh + t * PITCH);

        // 4 independent packed accumulator chains (2 per batch row)
        unsigned long long aA0 = 0ull, aB0 = 0ull, aA1 = 0ull, aB1 = 0ull;

        // k in [0, K_SMEM): W from shared
        #pragma unroll
        for (int i = 0; i < K_SMEM / 4; i++) {
            ulonglong2 w  = wv[i];
            ulonglong2 ha = h0v[i];
            ulonglong2 hb = h1v[i];
            aA0 = ffma2(w.x, ha.x, aA0);
            aB0 = ffma2(w.y, ha.y, aB0);
            aA1 = ffma2(w.x, hb.x, aA1);
            aB1 = ffma2(w.y, hb.y, aB1);
        }
        // k in [K_SMEM, 256): W from regs
        #pragma unroll
        for (int r = 0; r < K_REG / 4; r++) {
            ulonglong2 w  = wreg[r];
            ulonglong2 ha = h0v[K_SMEM / 4 + r];
            ulonglong2 hb = h1v[K_SMEM / 4 + r];
            aA0 = ffma2(w.x, ha.x, aA0);
            aB0 = ffma2(w.y, ha.y, aB0);
            aA1 = ffma2(w.x, hb.x, aA1);
            aB1 = ffma2(w.y, hb.y, aB1);
        }

        float2 fA0 = u2f(aA0), fB0 = u2f(aB0);
        float2 fA1 = u2f(aA1), fB1 = u2f(aB1);
        float h0 = fmaxf(xa + ((fA0.x + fA0.y) + (fB0.x + fB0.y)), 0.f);
        float h1 = fmaxf(xb + ((fA1.x + fA1.y) + (fB1.x + fB1.y)), 0.f);

        const int time = dir ? (T - 1 - s) : s;
        out_t[((size_t)b0 * T + time) * (2 * H)] = h0;
        out_t[((size_t)(b0 + 1) * T + time) * (2 * H)] = h1;

        const int nb = buf ^ 1;
        hs[nb * 512 + t]       = h0;
        hs[nb * 512 + 256 + t] = h1;
        __syncthreads();

        buf = nb;
        xa = nxa;
        xb = nxb;
    }
}

// ---------------------------------------------------------------------------
extern "C" void kernel_launch(void* const* d_in, const int* in_sizes, int n_in,
                              void* d_out, int out_size)
{
    const float* x      = (const float*)d_in[0];
    const float* w_ih_f = (const float*)d_in[1];
    const float* w_hh_f = (const float*)d_in[2];
    const float* b_ih_f = (const float*)d_in[3];
    const float* b_hh_f = (const float*)d_in[4];
    const float* w_ih_b = (const float*)d_in[5];
    const float* w_hh_b = (const float*)d_in[6];
    const float* b_ih_b = (const float*)d_in[7];
    const float* b_hh_b = (const float*)d_in[8];
    float* out = (float*)d_out;

    static bool attr_set = false;
    const int smem_bytes = 256 * PITCH * 4 + 2 * 2 * 256 * 4;  // 106,496 B
    if (!attr_set) {
        cudaFuncSetAttribute(rnn_kernel, cudaFuncAttributeMaxDynamicSharedMemorySize, smem_bytes);
        attr_set = true;
    }

    // 1) input projection: T blocks, 2 neurons/thread, both dirs per block
    proj_kernel<<<T, 256>>>(x, w_ih_f, b_ih_f, b_hh_f, w_ih_b, b_ih_b, b_hh_b);

    // 2) recurrence: 128 CTAs (64 per direction, 2 batch rows each)
    rnn_kernel<<<128, 256, smem_bytes>>>(w_hh_f, w_hh_b, out);
}

// round 11
// speedup vs baseline: 1.2829x; 1.0780x over previous
#include <cuda_runtime.h>
#include <cstdint>

// Problem constants
#define B 128
#define T 512
#define I 50
#define H 256
#define K_SMEM 96           // k-range of W kept in shared memory (rnn role)
#define K_REG  160          // k-range of W kept in registers (rnn role)
#define PITCH 100           // smem pitch in floats (conflict-free LDS.128)
#define NPROD 20            // producer CTAs (SMs left idle by the 128 rnn CTAs)
#define IPAD 52

// Scratch: xp[dir][t][b][h]  (fp32), 134 MB
__device__ float g_xp[2u * T * B * H];
// per-8-timestep completion counters: group g done when g_flag8[g] == 8
__device__ int g_flag8[T / 8];

// ---------------------------------------------------------------------------
// packed fp32x2 helpers (Blackwell)
// ---------------------------------------------------------------------------
__device__ __forceinline__ unsigned long long ffma2(unsigned long long a,
                                                    unsigned long long b,
                                                    unsigned long long c) {
    unsigned long long d;
    asm("fma.rn.f32x2 %0, %1, %2, %3;" : "=l"(d) : "l"(a), "l"(b), "l"(c));
    return d;
}
__device__ __forceinline__ float2 u2f(unsigned long long v) {
    float2 f;
    asm("mov.b64 {%0, %1}, %2;" : "=f"(f.x), "=f"(f.y) : "l"(v));
    return f;
}
__device__ __forceinline__ unsigned long long f2u(float lo, float hi) {
    unsigned long long v;
    asm("mov.b64 %0, {%1, %2};" : "=l"(v) : "f"(lo), "f"(hi));
    return v;
}
__device__ __forceinline__ float ld_cg(const float* p) {
    float v;
    asm volatile("ld.global.cg.f32 %0, [%1];" : "=f"(v) : "l"(p));
    return v;
}
__device__ __forceinline__ void spin_group(int g) {
    const int* fp = &g_flag8[g];
    int v;
    while (true) {
        asm volatile("ld.acquire.gpu.global.s32 %0, [%1];" : "=r"(v) : "l"(fp));
        if (v >= 8) break;
        __nanosleep(128);
    }
}

// ---------------------------------------------------------------------------
// Producer role (blocks 0..NPROD-1): block w computes xp[fwd][s] AND xp[bwd][s]
// for s = w, w+20, ... Thread: h2 = tid&127 -> neurons {2h2, 2h2+1}, dir = tid>>7.
// After each timestep: fence + atomicAdd on its 8-group counter.
// ---------------------------------------------------------------------------
__device__ __forceinline__ void proj_role(
    int w, int tid, float* xs,
    const float* __restrict__ x,
    const float* __restrict__ w_ih_f, const float* __restrict__ b_ih_f, const float* __restrict__ b_hh_f,
    const float* __restrict__ w_ih_b, const float* __restrict__ b_ih_b, const float* __restrict__ b_hh_b)
{
    const int h2  = tid & 127;
    const int dir = tid >> 7;
    const int lt  = tid & 127;       // lane within direction half

    // weight rows (this thread's direction), packed pairs, zero-padded
    const float* wsrc = dir ? w_ih_b : w_ih_f;
    const float* bih  = dir ? b_ih_b : b_ih_f;
    const float* bhh  = dir ? b_hh_b : b_hh_f;
    unsigned long long w0[26], w1[26];
    {
        const float* p0 = wsrc + (size_t)(2 * h2) * I;
        const float* p1 = wsrc + (size_t)(2 * h2 + 1) * I;
        #pragma unroll
        for (int i = 0; i < 25; i++) {
            w0[i] = f2u(p0[2 * i], p0[2 * i + 1]);
            w1[i] = f2u(p1[2 * i], p1[2 * i + 1]);
        }
        w0[25] = 0ull;
        w1[25] = 0ull;
    }
    const float bias0 = bih[2 * h2]     + bhh[2 * h2];
    const float bias1 = bih[2 * h2 + 1] + bhh[2 * h2 + 1];

    // zero the two staging buffers once (covers pad lanes)
    for (int i = tid; i < 2 * B * IPAD; i += 256) xs[i] = 0.f;
    __syncthreads();

    for (int s = w; s < T; s += NPROD) {
        // dir-half d stages x[:, tsrc_d, :] into xs[d]
        const int tsrc = dir ? (T - 1 - s) : s;
        float* xsd = xs + dir * (B * IPAD);
        for (int idx = lt; idx < B * I; idx += 128) {
            int b = idx / I;
            int i = idx - b * I;
            xsd[b * IPAD + i] = x[((size_t)b * T + tsrc) * I + i];
        }
        __syncthreads();

        float* xp_out = g_xp + (((size_t)dir * T + s) * B) * H + 2 * h2;
        const float* xsme = xs + dir * (B * IPAD);
        #pragma unroll 2
        for (int b = 0; b < B; b++) {
            const ulonglong2* xb = reinterpret_cast<const ulonglong2*>(&xsme[b * IPAD]);
            unsigned long long a00 = 0ull, a01 = 0ull, a10 = 0ull, a11 = 0ull;
            #pragma unroll
            for (int i = 0; i < 13; i++) {
                ulonglong2 xv = xb[i];
                a00 = ffma2(xv.x, w0[2 * i],     a00);
                a01 = ffma2(xv.y, w0[2 * i + 1], a01);
                a10 = ffma2(xv.x, w1[2 * i],     a10);
                a11 = ffma2(xv.y, w1[2 * i + 1], a11);
            }
            float2 f00 = u2f(a00), f01 = u2f(a01);
            float2 f10 = u2f(a10), f11 = u2f(a11);
            float2 o;
            o.x = bias0 + ((f00.x + f00.y) + (f01.x + f01.y));
            o.y = bias1 + ((f10.x + f10.y) + (f11.x + f11.y));
            *reinterpret_cast<float2*>(xp_out + (size_t)b * H) = o;
        }

        __syncthreads();                 // all stores of this task issued
        if (tid == 0) {
            __threadfence();             // publish xp before flag
            atomicAdd(&g_flag8[s >> 3], 1);
        }
        // next iteration's staging waits on the same barrier cadence
    }
}

// ---------------------------------------------------------------------------
// Consumer role: BYTE-EXACT round-2 recurrence loop (781 us), with only:
//  - xp loads via ld.global.cg (L2-coherent)
//  - a group-flag wait every 8 steps (rarely-taken branch)
// DO NOT otherwise modify (R7/R9: any reorder regresses 15-25%).
// ---------------------------------------------------------------------------
__device__ __forceinline__ void rnn_role(
    int bi, int t, float* sm,
    const float* __restrict__ w_hh_f,
    const float* __restrict__ w_hh_b,
    float* __restrict__ out)
{
    float* Wsh = sm;                       // [256][PITCH]
    float* hs  = sm + 256 * PITCH;         // [2 buf][2 rows][256]

    const int dir = bi >> 6;
    const int j   = bi & 63;
    const int b0  = 2 * j;

    const float* __restrict__ W = dir ? w_hh_b : w_hh_f;

    // W[:, 0:K_SMEM] -> smem
    for (int idx = t; idx < 256 * K_SMEM; idx += 256) {
        int n = idx / K_SMEM;
        int k = idx - n * K_SMEM;
        Wsh[n * PITCH + k] = W[n * H + k];
    }
    // W[t, K_SMEM:256] -> regs, as packed (k,k+1) pairs
    ulonglong2 wreg[K_REG / 4];
    {
        const ulonglong2* wrow = reinterpret_cast<const ulonglong2*>(W + (size_t)t * H + K_SMEM);
        #pragma unroll
        for (int r = 0; r < K_REG / 4; r++) wreg[r] = wrow[r];
    }
    hs[0 * 512 + 0 * 256 + t] = 0.f;
    hs[0 * 512 + 1 * 256 + t] = 0.f;
    __syncthreads();

    const float* xp0 = g_xp + ((size_t)dir * T * B + b0) * H + t;
    const float* xp1 = xp0 + H;
    const size_t step_stride = (size_t)B * H;

    spin_group(0);                         // timesteps 0..7 ready
    float xa = ld_cg(xp0);
    float xb = ld_cg(xp1);

    float* out_t = out + (size_t)dir * H + t;

    int buf = 0;
    for (int s = 0; s < T; s++) {
        if ((s & 7) == 0 && s < T - 8) spin_group((s >> 3) + 1);

        float nxa = 0.f, nxb = 0.f;
        if (s < T - 1) {
            nxa = ld_cg(xp0 + (size_t)(s + 1) * step_stride);
            nxb = ld_cg(xp1 + (size_t)(s + 1) * step_stride);
        }

        const ulonglong2* h0v = reinterpret_cast<const ulonglong2*>(hs + buf * 512);
        const ulonglong2* h1v = reinterpret_cast<const ulonglong2*>(hs + buf * 512 + 256);
        const ulonglong2* wv  = reinterpret_cast<const ulonglong2*>(Wsh + t * PITCH);

        unsigned long long aA0 = 0ull, aB0 = 0ull, aA1 = 0ull, aB1 = 0ull;

        #pragma unroll
        for (int i = 0; i < K_SMEM / 4; i++) {
            ulonglong2 w  = wv[i];
            ulonglong2 ha = h0v[i];
            ulonglong2 hb = h1v[i];
            aA0 = ffma2(w.x, ha.x, aA0);
            aB0 = ffma2(w.y, ha.y, aB0);
            aA1 = ffma2(w.x, hb.x, aA1);
            aB1 = ffma2(w.y, hb.y, aB1);
        }
        #pragma unroll
        for (int r = 0; r < K_REG / 4; r++) {
            ulonglong2 w  = wreg[r];
            ulonglong2 ha = h0v[K_SMEM / 4 + r];
            ulonglong2 hb = h1v[K_SMEM / 4 + r];
            aA0 = ffma2(w.x, ha.x, aA0);
            aB0 = ffma2(w.y, ha.y, aB0);
            aA1 = ffma2(w.x, hb.x, aA1);
            aB1 = ffma2(w.y, hb.y, aB1);
        }

        float2 fA0 = u2f(aA0), fB0 = u2f(aB0);
        float2 fA1 = u2f(aA1), fB1 = u2f(aB1);
        float h0 = fmaxf(xa + ((fA0.x + fA0.y) + (fB0.x + fB0.y)), 0.f);
        float h1 = fmaxf(xb + ((fA1.x + fA1.y) + (fB1.x + fB1.y)), 0.f);

        const int time = dir ? (T - 1 - s) : s;
        out_t[((size_t)b0 * T + time) * (2 * H)] = h0;
        out_t[((size_t)(b0 + 1) * T + time) * (2 * H)] = h1;

        const int nb = buf ^ 1;
        hs[nb * 512 + t]       = h0;
        hs[nb * 512 + 256 + t] = h1;
        __syncthreads();

        buf = nb;
        xa = nxa;
        xb = nxb;
    }
}

// ---------------------------------------------------------------------------
// Fused kernel: blocks 0..19 produce xp, blocks 20..147 run the recurrence.
// Grid 148 <= SM count -> all CTAs co-resident -> no deadlock.
// ---------------------------------------------------------------------------
__global__ __launch_bounds__(256, 1) void fused_kernel(
    const float* __restrict__ x,
    const float* __restrict__ w_ih_f, const float* __restrict__ b_ih_f, const float* __restrict__ b_hh_f,
    const float* __restrict__ w_ih_b, const float* __restrict__ b_ih_b, const float* __restrict__ b_hh_b,
    const float* __restrict__ w_hh_f, const float* __restrict__ w_hh_b,
    float* __restrict__ out)
{
    extern __shared__ float sm[];
    const int bi  = blockIdx.x;
    const int tid = threadIdx.x;

    if (bi < NPROD) {
        proj_role(bi, tid, sm, x, w_ih_f, b_ih_f, b_hh_f, w_ih_b, b_ih_b, b_hh_b);
    } else {
        rnn_role(bi - NPROD, tid, sm, w_hh_f, w_hh_b, out);
    }
}

// ---------------------------------------------------------------------------
extern "C" void kernel_launch(void* const* d_in, const int* in_sizes, int n_in,
                              void* d_out, int out_size)
{
    const float* x      = (const float*)d_in[0];
    const float* w_ih_f = (const float*)d_in[1];
    const float* w_hh_f = (const float*)d_in[2];
    const float* b_ih_f = (const float*)d_in[3];
    const float* b_hh_f = (const float*)d_in[4];
    const float* w_ih_b = (const float*)d_in[5];
    const float* w_hh_b = (const float*)d_in[6];
    const float* b_ih_b = (const float*)d_in[7];
    const float* b_hh_b = (const float*)d_in[8];
    float* out = (float*)d_out;

    static bool init_done = false;
    static void* flag_addr = nullptr;
    const int smem_bytes = 256 * PITCH * 4 + 2 * 2 * 256 * 4;  // 106,496 B (>= proj's 53 KB)
    if (!init_done) {
        cudaFuncSetAttribute(fused_kernel, cudaFuncAttributeMaxDynamicSharedMemorySize, smem_bytes);
        cudaGetSymbolAddress(&flag_addr, g_flag8);
        init_done = true;
    }

    // zero the pipeline flags (graph-capturable memset node)
    cudaMemsetAsync(flag_addr, 0, sizeof(int) * (T / 8));

    // one fused launch: 20 producer CTAs + 128 recurrence CTAs
    fused_kernel<<<NPROD + 128, 256, smem_bytes>>>(
        x, w_ih_f, b_ih_f, b_hh_f, w_ih_b, b_ih_b, b_hh_b, w_hh_f, w_hh_b, out);
}